// round 1
// baseline (speedup 1.0000x reference)
#include <cuda_runtime.h>
#include <cstdint>

#define EDGES  800000
#define NODES  50000
#define EPSN   1e-12f

// ---------------- scratch (static device globals; no allocation) ----------------
static __device__ float g_M1[EDGES * 128];   // layer1 messages
static __device__ float g_EH[EDGES * 128];   // relu(edge linear 1) -> layer2 edge input
static __device__ float g_R1[EDGES * 128];   // layer1 MLP hidden
static __device__ float g_W2[EDGES * 256];   // layer2 edge weights
static __device__ float g_M2[EDGES * 256];   // layer2 messages
static __device__ float g_R3[EDGES * 256];   // layer2 MLP hidden
static __device__ float g_s1[NODES * 128];   // layer1 segment sum
static __device__ float g_s2[NODES * 256];   // layer2 segment sum
static __device__ float g_h1[NODES * 256];   // layer1 node output (post relu)
static __device__ float g_A1[NODES * 256];   // concat input for node linear 1
static __device__ float g_A2[NODES * 512];   // concat input for node linear 2
static __device__ float g_cnt[NODES];        // in-degree (float)

// ---------------- f32x2 packed helpers ----------------
static __device__ __forceinline__ unsigned long long pk2(float x, float y) {
    unsigned long long r;
    asm("mov.b64 %0, {%1, %2};" : "=l"(r) : "f"(x), "f"(y));
    return r;
}
static __device__ __forceinline__ void upk2(unsigned long long v, float &x, float &y) {
    asm("mov.b64 {%0, %1}, %2;" : "=f"(x), "=f"(y) : "l"(v));
}
static __device__ __forceinline__ unsigned long long ffma2(unsigned long long a,
                                                           unsigned long long b,
                                                           unsigned long long c) {
    unsigned long long d;
    asm("fma.rn.f32x2 %0, %1, %2, %3;" : "=l"(d) : "l"(a), "l"(b), "l"(c));
    return d;
}

// ---------------- zero scratch accumulators ----------------
__global__ void zero_k(float *s1, float *s2, float *cnt) {
    int i = blockIdx.x * blockDim.x + threadIdx.x;
    int n1 = NODES * 128, n2 = NODES * 256;
    if (i < n1) s1[i] = 0.0f;
    if (i < n2) s2[i] = 0.0f;
    if (i < NODES) cnt[i] = 0.0f;
}

// ---------------- degree count ----------------
__global__ void cnt_k(const int *__restrict__ dst, float *__restrict__ cnt) {
    int i = blockIdx.x * blockDim.x + threadIdx.x;
    if (i < EDGES) atomicAdd(&cnt[dst[i]], 1.0f);
}

// ---------------- layer1 edge kernel: cos-gated message + relu(edge lin) ----------------
__global__ __launch_bounds__(256) void edge1_k(
    const float *__restrict__ nf, const float *__restrict__ ef,
    const int *__restrict__ src, const int *__restrict__ dst,
    const float *__restrict__ We1, const float *__restrict__ be1,
    float *__restrict__ M1, float *__restrict__ EH) {
    int e = blockIdx.x * 8 + (threadIdx.x >> 5);
    if (e >= EDGES) return;
    int l = threadIdx.x & 31;
    int s = src[e], d = dst[e];
    const float4 hs = *(const float4 *)(nf + (size_t)s * 128 + l * 4);
    const float4 hd = *(const float4 *)(nf + (size_t)d * 128 + l * 4);
    float ss = hs.x * hs.x + hs.y * hs.y + hs.z * hs.z + hs.w * hs.w;
    float dd = hd.x * hd.x + hd.y * hd.y + hd.z * hd.z + hd.w * hd.w;
    float sd = hs.x * hd.x + hs.y * hd.y + hs.z * hd.z + hs.w * hd.w;
#pragma unroll
    for (int o = 16; o > 0; o >>= 1) {
        ss += __shfl_xor_sync(0xffffffffu, ss, o);
        dd += __shfl_xor_sync(0xffffffffu, dd, o);
        sd += __shfl_xor_sync(0xffffffffu, sd, o);
    }
    float cosv = sd / (fmaxf(sqrtf(ss), EPSN) * fmaxf(sqrtf(dd), EPSN));
    float e0 = ef[2 * e], e1 = ef[2 * e + 1];
    int j = l * 4;
    float4 w;
    w.x = e0 * We1[j + 0] + e1 * We1[128 + j + 0] + be1[j + 0];
    w.y = e0 * We1[j + 1] + e1 * We1[128 + j + 1] + be1[j + 1];
    w.z = e0 * We1[j + 2] + e1 * We1[128 + j + 2] + be1[j + 2];
    w.w = e0 * We1[j + 3] + e1 * We1[128 + j + 3] + be1[j + 3];
    float4 m;
    m.x = cosv * w.x * hs.x; m.y = cosv * w.y * hs.y;
    m.z = cosv * w.z * hs.z; m.w = cosv * w.w * hs.w;
    *(float4 *)(M1 + (size_t)e * 128 + j) = m;
    float4 r;
    r.x = fmaxf(w.x, 0.0f); r.y = fmaxf(w.y, 0.0f);
    r.z = fmaxf(w.z, 0.0f); r.w = fmaxf(w.w, 0.0f);
    *(float4 *)(EH + (size_t)e * 128 + j) = r;
}

// ---------------- layer2 edge kernel ----------------
__global__ __launch_bounds__(256) void edge2_k(
    const int *__restrict__ src, const int *__restrict__ dst,
    const float *__restrict__ h1, const float *__restrict__ W2,
    float *__restrict__ M2) {
    int e = blockIdx.x * 8 + (threadIdx.x >> 5);
    if (e >= EDGES) return;
    int l = threadIdx.x & 31;
    int s = src[e], d = dst[e];
    const float4 s0 = *(const float4 *)(h1 + (size_t)s * 256 + l * 4);
    const float4 s1v = *(const float4 *)(h1 + (size_t)s * 256 + 128 + l * 4);
    const float4 d0 = *(const float4 *)(h1 + (size_t)d * 256 + l * 4);
    const float4 d1 = *(const float4 *)(h1 + (size_t)d * 256 + 128 + l * 4);
    float ss = s0.x * s0.x + s0.y * s0.y + s0.z * s0.z + s0.w * s0.w
             + s1v.x * s1v.x + s1v.y * s1v.y + s1v.z * s1v.z + s1v.w * s1v.w;
    float dd = d0.x * d0.x + d0.y * d0.y + d0.z * d0.z + d0.w * d0.w
             + d1.x * d1.x + d1.y * d1.y + d1.z * d1.z + d1.w * d1.w;
    float sd = s0.x * d0.x + s0.y * d0.y + s0.z * d0.z + s0.w * d0.w
             + s1v.x * d1.x + s1v.y * d1.y + s1v.z * d1.z + s1v.w * d1.w;
#pragma unroll
    for (int o = 16; o > 0; o >>= 1) {
        ss += __shfl_xor_sync(0xffffffffu, ss, o);
        dd += __shfl_xor_sync(0xffffffffu, dd, o);
        sd += __shfl_xor_sync(0xffffffffu, sd, o);
    }
    float cosv = sd / (fmaxf(sqrtf(ss), EPSN) * fmaxf(sqrtf(dd), EPSN));
    const float4 w0 = *(const float4 *)(W2 + (size_t)e * 256 + l * 4);
    const float4 w1 = *(const float4 *)(W2 + (size_t)e * 256 + 128 + l * 4);
    float4 m0, m1;
    m0.x = cosv * w0.x * s0.x; m0.y = cosv * w0.y * s0.y;
    m0.z = cosv * w0.z * s0.z; m0.w = cosv * w0.w * s0.w;
    m1.x = cosv * w1.x * s1v.x; m1.y = cosv * w1.y * s1v.y;
    m1.z = cosv * w1.z * s1v.z; m1.w = cosv * w1.w * s1v.w;
    *(float4 *)(M2 + (size_t)e * 256 + l * 4) = m0;
    *(float4 *)(M2 + (size_t)e * 256 + 128 + l * 4) = m1;
}

// ---------------- tiled GEMM: C = op(A @ B + bias) ----------------
// MODE 0: store (bias, no relu); MODE 1: store relu; MODE 2: relu + atomic scatter to C[dst[row]]
template <int MODE>
__global__ __launch_bounds__(256) void gemm_k(
    const float *__restrict__ A, const float *__restrict__ B,
    const float *__restrict__ bias, float *__restrict__ C,
    int M, int K, int N, const int *__restrict__ dIdx) {
    __shared__ float As[16][128];
    __shared__ float Bs[16][128];
    const int tid = threadIdx.x;
    const int row0 = blockIdx.x * 128, col0 = blockIdx.y * 128;
    const int arow = tid >> 1, ac0 = (tid & 1) << 3;
    const int brow = tid >> 4, bc0 = (tid & 15) << 3;
    const int tm = (tid >> 4) << 3, tn = (tid & 15) << 3;
    unsigned long long acc[8][4];
#pragma unroll
    for (int i = 0; i < 8; i++)
#pragma unroll
        for (int j = 0; j < 4; j++) acc[i][j] = 0ull;
    const bool aval = (row0 + arow) < M;
    const float *Aptr = A + (size_t)(row0 + arow) * K + ac0;
    const float *Bptr = B + (size_t)brow * N + col0 + bc0;
    for (int k0 = 0; k0 < K; k0 += 16) {
        float4 a0 = make_float4(0.f, 0.f, 0.f, 0.f), a1 = a0;
        if (aval) {
            a0 = *(const float4 *)(Aptr + k0);
            a1 = *(const float4 *)(Aptr + k0 + 4);
        }
        float4 b0 = *(const float4 *)(Bptr + (size_t)k0 * N);
        float4 b1 = *(const float4 *)(Bptr + (size_t)k0 * N + 4);
        __syncthreads();
        As[ac0 + 0][arow] = a0.x; As[ac0 + 1][arow] = a0.y;
        As[ac0 + 2][arow] = a0.z; As[ac0 + 3][arow] = a0.w;
        As[ac0 + 4][arow] = a1.x; As[ac0 + 5][arow] = a1.y;
        As[ac0 + 6][arow] = a1.z; As[ac0 + 7][arow] = a1.w;
        *(float4 *)&Bs[brow][bc0] = b0;
        *(float4 *)&Bs[brow][bc0 + 4] = b1;
        __syncthreads();
#pragma unroll
        for (int kk = 0; kk < 16; kk++) {
            float4 af0 = *(const float4 *)&As[kk][tm];
            float4 af1 = *(const float4 *)&As[kk][tm + 4];
            float4 bf0 = *(const float4 *)&Bs[kk][tn];
            float4 bf1 = *(const float4 *)&Bs[kk][tn + 4];
            unsigned long long b2[4] = {pk2(bf0.x, bf0.y), pk2(bf0.z, bf0.w),
                                        pk2(bf1.x, bf1.y), pk2(bf1.z, bf1.w)};
            float av[8] = {af0.x, af0.y, af0.z, af0.w, af1.x, af1.y, af1.z, af1.w};
#pragma unroll
            for (int i = 0; i < 8; i++) {
                unsigned long long a2 = pk2(av[i], av[i]);
#pragma unroll
                for (int j = 0; j < 4; j++) acc[i][j] = ffma2(a2, b2[j], acc[i][j]);
            }
        }
    }
    float bv[8];
#pragma unroll
    for (int j = 0; j < 8; j++) bv[j] = bias[col0 + tn + j];
#pragma unroll
    for (int i = 0; i < 8; i++) {
        int gr = row0 + tm + i;
        if (gr >= M) continue;
        float v[8];
#pragma unroll
        for (int j = 0; j < 4; j++) upk2(acc[i][j], v[2 * j], v[2 * j + 1]);
#pragma unroll
        for (int j = 0; j < 8; j++) {
            v[j] += bv[j];
            if (MODE >= 1) v[j] = fmaxf(v[j], 0.0f);
        }
        if (MODE == 2) {
            int d = dIdx[gr];
            float *p = C + (size_t)d * N + col0 + tn;
#pragma unroll
            for (int j = 0; j < 8; j++) atomicAdd(p + j, v[j]);
        } else {
            float *p = C + (size_t)gr * N + col0 + tn;
            *(float4 *)(p) = make_float4(v[0], v[1], v[2], v[3]);
            *(float4 *)(p + 4) = make_float4(v[4], v[5], v[6], v[7]);
        }
    }
}

// ---------------- concat builders (with mean division) ----------------
__global__ void build1_k(const float *__restrict__ nf, const float *__restrict__ s1,
                         const float *__restrict__ cnt, float *__restrict__ A1) {
    int idx = blockIdx.x * blockDim.x + threadIdx.x;  // float4 units
    if (idx >= NODES * 64) return;
    int n = idx >> 6;
    int c = (idx & 63) * 4;
    float4 v;
    if (c < 128) {
        v = *(const float4 *)(nf + (size_t)n * 128 + c);
    } else {
        float inv = 1.0f / fmaxf(cnt[n], 1.0f);
        float4 t = *(const float4 *)(s1 + (size_t)n * 128 + (c - 128));
        v = make_float4(t.x * inv, t.y * inv, t.z * inv, t.w * inv);
    }
    *(float4 *)(A1 + (size_t)n * 256 + c) = v;
}

__global__ void build2_k(const float *__restrict__ h1, const float *__restrict__ s2,
                         const float *__restrict__ cnt, float *__restrict__ A2) {
    int idx = blockIdx.x * blockDim.x + threadIdx.x;  // float4 units
    if (idx >= NODES * 128) return;
    int n = idx >> 7;
    int c = (idx & 127) * 4;
    float4 v;
    if (c < 256) {
        v = *(const float4 *)(h1 + (size_t)n * 256 + c);
    } else {
        float inv = 1.0f / fmaxf(cnt[n], 1.0f);
        float4 t = *(const float4 *)(s2 + (size_t)n * 256 + (c - 256));
        v = make_float4(t.x * inv, t.y * inv, t.z * inv, t.w * inv);
    }
    *(float4 *)(A2 + (size_t)n * 512 + c) = v;
}

// ---------------- final small GEMM: out = A2 @ Wl2 + bl2  [50000,512]@[512,32] ----------------
__global__ __launch_bounds__(256) void out_k(const float *__restrict__ A2,
                                             const float *__restrict__ Wl2,
                                             const float *__restrict__ bl2,
                                             float *__restrict__ out) {
    int row = blockIdx.x * 8 + (threadIdx.x >> 5);
    int c = threadIdx.x & 31;
    if (row >= NODES) return;
    const float *a = A2 + (size_t)row * 512;
    float acc = bl2[c];
#pragma unroll 4
    for (int k = 0; k < 512; k += 4) {
        float4 av = *(const float4 *)(a + k);
        acc += av.x * Wl2[(k + 0) * 32 + c];
        acc += av.y * Wl2[(k + 1) * 32 + c];
        acc += av.z * Wl2[(k + 2) * 32 + c];
        acc += av.w * Wl2[(k + 3) * 32 + c];
    }
    out[(size_t)row * 32 + c] = acc;
}

// ---------------- launch ----------------
extern "C" void kernel_launch(void *const *d_in, const int *in_sizes, int n_in,
                              void *d_out, int out_size) {
    const float *nf = (const float *)d_in[0];
    const float *ef = (const float *)d_in[1];
    const int *src = (const int *)d_in[2];
    const int *dst = (const int *)d_in[3];
    const float *We1 = (const float *)d_in[4];
    const float *be1 = (const float *)d_in[5];
    const float *Wr1a = (const float *)d_in[6];
    const float *br1a = (const float *)d_in[7];
    const float *Wr1b = (const float *)d_in[8];
    const float *br1b = (const float *)d_in[9];
    const float *Wl1 = (const float *)d_in[10];
    const float *bl1 = (const float *)d_in[11];
    const float *We2 = (const float *)d_in[12];
    const float *be2 = (const float *)d_in[13];
    const float *Wr2a = (const float *)d_in[14];
    const float *br2a = (const float *)d_in[15];
    const float *Wr2b = (const float *)d_in[16];
    const float *br2b = (const float *)d_in[17];
    const float *Wl2 = (const float *)d_in[18];
    const float *bl2 = (const float *)d_in[19];
    float *out = (float *)d_out;

    void *pM1, *pEH, *pR1, *pW2, *pM2, *pR3, *pS1, *pS2, *pH1, *pA1, *pA2, *pCnt;
    cudaGetSymbolAddress(&pM1, g_M1);
    cudaGetSymbolAddress(&pEH, g_EH);
    cudaGetSymbolAddress(&pR1, g_R1);
    cudaGetSymbolAddress(&pW2, g_W2);
    cudaGetSymbolAddress(&pM2, g_M2);
    cudaGetSymbolAddress(&pR3, g_R3);
    cudaGetSymbolAddress(&pS1, g_s1);
    cudaGetSymbolAddress(&pS2, g_s2);
    cudaGetSymbolAddress(&pH1, g_h1);
    cudaGetSymbolAddress(&pA1, g_A1);
    cudaGetSymbolAddress(&pA2, g_A2);
    cudaGetSymbolAddress(&pCnt, g_cnt);

    // zero accumulators
    zero_k<<<(NODES * 256 + 255) / 256, 256>>>((float *)pS1, (float *)pS2, (float *)pCnt);
    // degree
    cnt_k<<<(EDGES + 255) / 256, 256>>>(dst, (float *)pCnt);
    // layer 1
    edge1_k<<<EDGES / 8, 256>>>(nf, ef, src, dst, We1, be1, (float *)pM1, (float *)pEH);
    gemm_k<1><<<dim3(EDGES / 128, 1), 256>>>((float *)pM1, Wr1a, br1a, (float *)pR1,
                                             EDGES, 128, 128, nullptr);
    gemm_k<2><<<dim3(EDGES / 128, 1), 256>>>((float *)pR1, Wr1b, br1b, (float *)pS1,
                                             EDGES, 128, 128, dst);
    build1_k<<<(NODES * 64 + 255) / 256, 256>>>(nf, (float *)pS1, (float *)pCnt, (float *)pA1);
    gemm_k<1><<<dim3((NODES + 127) / 128, 2), 256>>>((float *)pA1, Wl1, bl1, (float *)pH1,
                                                     NODES, 256, 256, nullptr);
    // layer 2
    gemm_k<0><<<dim3(EDGES / 128, 2), 256>>>((float *)pEH, We2, be2, (float *)pW2,
                                             EDGES, 128, 256, nullptr);
    edge2_k<<<EDGES / 8, 256>>>(src, dst, (float *)pH1, (float *)pW2, (float *)pM2);
    gemm_k<1><<<dim3(EDGES / 128, 2), 256>>>((float *)pM2, Wr2a, br2a, (float *)pR3,
                                             EDGES, 256, 256, nullptr);
    gemm_k<2><<<dim3(EDGES / 128, 2), 256>>>((float *)pR3, Wr2b, br2b, (float *)pS2,
                                             EDGES, 256, 256, dst);
    build2_k<<<(NODES * 128 + 255) / 256, 256>>>((float *)pH1, (float *)pS2, (float *)pCnt,
                                                 (float *)pA2);
    out_k<<<(NODES + 7) / 8, 256>>>((float *)pA2, Wl2, bl2, out);
}

// round 6
// speedup vs baseline: 2.1502x; 2.1502x over previous
#include <cuda_runtime.h>
#include <cstdint>

#define EDGES  800000
#define NODES  50000
#define EPSN   1e-12f

// ---------------- scratch (static device globals; no allocation) ----------------
static __device__ float g_M1[EDGES * 128];
static __device__ float g_EH[EDGES * 128];
static __device__ float g_R1[EDGES * 128];
static __device__ float g_W2[EDGES * 256];
static __device__ float g_M2[EDGES * 256];
static __device__ float g_R3[EDGES * 256];
static __device__ float g_s1[NODES * 128];
static __device__ float g_s2[NODES * 256];
static __device__ float g_h1[NODES * 256];
static __device__ float g_A1[NODES * 256];
static __device__ float g_A2[NODES * 512];
static __device__ float g_cnt[NODES];
// transposed weights [N][K] K-major
static __device__ float g_T1a[128 * 128];
static __device__ float g_T1b[128 * 128];
static __device__ float g_Te2[256 * 128];
static __device__ float g_T2a[256 * 256];
static __device__ float g_T2b[256 * 256];
static __device__ float g_Tl1[256 * 256];

// ---------------- mma.sync helpers (sm_80+ features only) ----------------
static __device__ __forceinline__ void mma_tf32(float* c, const uint32_t* a, const uint32_t* b) {
    asm volatile(
        "mma.sync.aligned.m16n8k8.row.col.f32.tf32.tf32.f32 "
        "{%0,%1,%2,%3}, {%4,%5,%6,%7}, {%8,%9}, {%0,%1,%2,%3};"
        : "+f"(c[0]), "+f"(c[1]), "+f"(c[2]), "+f"(c[3])
        : "r"(a[0]), "r"(a[1]), "r"(a[2]), "r"(a[3]), "r"(b[0]), "r"(b[1]));
}
static __device__ __forceinline__ uint32_t f2tf(float f) {
    uint32_t u;
    asm("cvt.rna.tf32.f32 %0, %1;" : "=r"(u) : "f"(f));
    return u;
}
static __device__ __forceinline__ void red2(float* p, float x, float y) {
    asm volatile("red.global.add.v2.f32 [%0], {%1, %2};" :: "l"(p), "f"(x), "f"(y) : "memory");
}

// ---------------- tensor-core GEMM: C = op(A[M,K] @ Bt[NT,K]^T + bias) ----------------
// Block tile 128x128 (grid.y covers NT/128). 8 warps: 4 along M x 2 along N; warp tile 32x64.
// MODE 0: store; 1: store relu; 2: relu + atomic scatter rows to C[dIdx[row]]
template <int MODE>
__global__ __launch_bounds__(256)
void gemm_mma(const float* __restrict__ A, const float* __restrict__ Bt,
              const float* __restrict__ bias, float* __restrict__ C,
              int M, int K, int NT, const int* __restrict__ dIdx) {
    __shared__ uint32_t As[128][36];
    __shared__ uint32_t Bs[128][36];
    const int tid = threadIdx.x;
    const int wid = tid >> 5, lane = tid & 31;
    const int g = lane >> 2, t = lane & 3;
    const int warpM = wid & 3, warpN = wid >> 2;
    const int row0 = blockIdx.x * 128;
    const int col0 = blockIdx.y * 128;

    float c[2][8][4];
#pragma unroll
    for (int mt = 0; mt < 2; mt++)
#pragma unroll
        for (int nt = 0; nt < 8; nt++)
#pragma unroll
            for (int i = 0; i < 4; i++) c[mt][nt][i] = 0.0f;

    // global->reg staging: each thread owns one row (tid>>1) and 16 cols ((tid&1)*16)
    const int lrow = tid >> 1;
    const int lcol = (tid & 1) * 16;
    const bool av = (row0 + lrow) < M;
    const float* apt = A + (size_t)(row0 + lrow) * K + lcol;
    const float* bpt = Bt + (size_t)(col0 + lrow) * K + lcol;

    float4 ra[4], rb[4];
    const int nchunks = K >> 5;

    // prologue: load chunk 0
#pragma unroll
    for (int i = 0; i < 4; i++) {
        ra[i] = av ? *(const float4*)(apt + i * 4) : make_float4(0.f, 0.f, 0.f, 0.f);
        rb[i] = *(const float4*)(bpt + i * 4);
    }

    for (int ch = 0; ch < nchunks; ch++) {
        __syncthreads();   // previous chunk's compute done; smem free
        // store staged regs -> smem with tf32 rounding (vectorized)
#pragma unroll
        for (int i = 0; i < 4; i++) {
            uint4 ua = make_uint4(f2tf(ra[i].x), f2tf(ra[i].y), f2tf(ra[i].z), f2tf(ra[i].w));
            uint4 ub = make_uint4(f2tf(rb[i].x), f2tf(rb[i].y), f2tf(rb[i].z), f2tf(rb[i].w));
            *(uint4*)&As[lrow][lcol + i * 4] = ua;
            *(uint4*)&Bs[lrow][lcol + i * 4] = ub;
        }
        __syncthreads();   // smem ready
        // prefetch next chunk (overlaps with compute below via scoreboard)
        if (ch + 1 < nchunks) {
            const float* an = apt + (ch + 1) * 32;
            const float* bn = bpt + (ch + 1) * 32;
#pragma unroll
            for (int i = 0; i < 4; i++) {
                ra[i] = av ? *(const float4*)(an + i * 4) : make_float4(0.f, 0.f, 0.f, 0.f);
                rb[i] = *(const float4*)(bn + i * 4);
            }
        }
        // compute: 4 k-steps of 8
#pragma unroll
        for (int kk = 0; kk < 4; kk++) {
            const int k8 = kk * 8;
            uint32_t af[2][4], bf[8][2];
#pragma unroll
            for (int mt = 0; mt < 2; mt++) {
                const int r = warpM * 32 + mt * 16 + g;
                af[mt][0] = As[r][k8 + t];
                af[mt][1] = As[r + 8][k8 + t];
                af[mt][2] = As[r][k8 + t + 4];
                af[mt][3] = As[r + 8][k8 + t + 4];
            }
#pragma unroll
            for (int nt = 0; nt < 8; nt++) {
                const int n = warpN * 64 + nt * 8 + g;
                bf[nt][0] = Bs[n][k8 + t];
                bf[nt][1] = Bs[n][k8 + t + 4];
            }
#pragma unroll
            for (int mt = 0; mt < 2; mt++)
#pragma unroll
                for (int nt = 0; nt < 8; nt++)
                    mma_tf32(c[mt][nt], af[mt], bf[nt]);
        }
    }

    // epilogue
#pragma unroll
    for (int mt = 0; mt < 2; mt++) {
        const int r0 = row0 + warpM * 32 + mt * 16 + g;   // rows r0 and r0+8
        const bool v0r = r0 < M, v1r = (r0 + 8) < M;
        int dn0 = 0, dn1 = 0;
        if (MODE == 2) {
            dn0 = v0r ? dIdx[r0] : 0;
            dn1 = v1r ? dIdx[r0 + 8] : 0;
        }
#pragma unroll
        for (int nt = 0; nt < 8; nt++) {
            const int cn = col0 + warpN * 64 + nt * 8 + t * 2;
            const float b0 = bias[cn], b1 = bias[cn + 1];
            float v0 = c[mt][nt][0] + b0, v1 = c[mt][nt][1] + b1;
            float v2 = c[mt][nt][2] + b0, v3 = c[mt][nt][3] + b1;
            if (MODE >= 1) {
                v0 = fmaxf(v0, 0.f); v1 = fmaxf(v1, 0.f);
                v2 = fmaxf(v2, 0.f); v3 = fmaxf(v3, 0.f);
            }
            if (MODE == 2) {
                if (v0r) red2(C + (size_t)dn0 * NT + cn, v0, v1);
                if (v1r) red2(C + (size_t)dn1 * NT + cn, v2, v3);
            } else {
                if (v0r) *(float2*)(C + (size_t)r0 * NT + cn) = make_float2(v0, v1);
                if (v1r) *(float2*)(C + (size_t)(r0 + 8) * NT + cn) = make_float2(v2, v3);
            }
        }
    }
}

// ---------------- small kernels ----------------
__global__ void zero_k(float* s1, float* s2, float* cnt) {
    int i = blockIdx.x * blockDim.x + threadIdx.x;
    if (i < NODES * 128) s1[i] = 0.0f;
    if (i < NODES * 256) s2[i] = 0.0f;
    if (i < NODES) cnt[i] = 0.0f;
}

__global__ void cnt_k(const int* __restrict__ dst, float* __restrict__ cnt) {
    int i = blockIdx.x * blockDim.x + threadIdx.x;
    if (i < EDGES) atomicAdd(&cnt[dst[i]], 1.0f);
}

__global__ void transp_k(const float* __restrict__ in, float* __restrict__ out, int K, int N) {
    int i = blockIdx.x * blockDim.x + threadIdx.x;
    if (i < K * N) {
        int k = i / N, n = i % N;
        out[(size_t)n * K + k] = in[i];
    }
}

__global__ __launch_bounds__(256) void edge1_k(
    const float* __restrict__ nf, const float* __restrict__ ef,
    const int* __restrict__ src, const int* __restrict__ dst,
    const float* __restrict__ We1, const float* __restrict__ be1,
    float* __restrict__ M1, float* __restrict__ EH) {
    int e = blockIdx.x * 8 + (threadIdx.x >> 5);
    if (e >= EDGES) return;
    int l = threadIdx.x & 31;
    int s = src[e], d = dst[e];
    const float4 hs = *(const float4*)(nf + (size_t)s * 128 + l * 4);
    const float4 hd = *(const float4*)(nf + (size_t)d * 128 + l * 4);
    float ss = hs.x * hs.x + hs.y * hs.y + hs.z * hs.z + hs.w * hs.w;
    float dd = hd.x * hd.x + hd.y * hd.y + hd.z * hd.z + hd.w * hd.w;
    float sd = hs.x * hd.x + hs.y * hd.y + hs.z * hd.z + hs.w * hd.w;
#pragma unroll
    for (int o = 16; o > 0; o >>= 1) {
        ss += __shfl_xor_sync(0xffffffffu, ss, o);
        dd += __shfl_xor_sync(0xffffffffu, dd, o);
        sd += __shfl_xor_sync(0xffffffffu, sd, o);
    }
    float cosv = sd / (fmaxf(sqrtf(ss), EPSN) * fmaxf(sqrtf(dd), EPSN));
    float e0 = ef[2 * e], e1 = ef[2 * e + 1];
    int j = l * 4;
    float4 w;
    w.x = e0 * We1[j + 0] + e1 * We1[128 + j + 0] + be1[j + 0];
    w.y = e0 * We1[j + 1] + e1 * We1[128 + j + 1] + be1[j + 1];
    w.z = e0 * We1[j + 2] + e1 * We1[128 + j + 2] + be1[j + 2];
    w.w = e0 * We1[j + 3] + e1 * We1[128 + j + 3] + be1[j + 3];
    float4 m;
    m.x = cosv * w.x * hs.x; m.y = cosv * w.y * hs.y;
    m.z = cosv * w.z * hs.z; m.w = cosv * w.w * hs.w;
    *(float4*)(M1 + (size_t)e * 128 + j) = m;
    float4 r;
    r.x = fmaxf(w.x, 0.0f); r.y = fmaxf(w.y, 0.0f);
    r.z = fmaxf(w.z, 0.0f); r.w = fmaxf(w.w, 0.0f);
    *(float4*)(EH + (size_t)e * 128 + j) = r;
}

__global__ __launch_bounds__(256) void edge2_k(
    const int* __restrict__ src, const int* __restrict__ dst,
    const float* __restrict__ h1, const float* __restrict__ W2,
    float* __restrict__ M2) {
    int e = blockIdx.x * 8 + (threadIdx.x >> 5);
    if (e >= EDGES) return;
    int l = threadIdx.x & 31;
    int s = src[e], d = dst[e];
    const float4 s0 = *(const float4*)(h1 + (size_t)s * 256 + l * 4);
    const float4 s1v = *(const float4*)(h1 + (size_t)s * 256 + 128 + l * 4);
    const float4 d0 = *(const float4*)(h1 + (size_t)d * 256 + l * 4);
    const float4 d1 = *(const float4*)(h1 + (size_t)d * 256 + 128 + l * 4);
    float ss = s0.x * s0.x + s0.y * s0.y + s0.z * s0.z + s0.w * s0.w
             + s1v.x * s1v.x + s1v.y * s1v.y + s1v.z * s1v.z + s1v.w * s1v.w;
    float dd = d0.x * d0.x + d0.y * d0.y + d0.z * d0.z + d0.w * d0.w
             + d1.x * d1.x + d1.y * d1.y + d1.z * d1.z + d1.w * d1.w;
    float sd = s0.x * d0.x + s0.y * d0.y + s0.z * d0.z + s0.w * d0.w
             + s1v.x * d1.x + s1v.y * d1.y + s1v.z * d1.z + s1v.w * d1.w;
#pragma unroll
    for (int o = 16; o > 0; o >>= 1) {
        ss += __shfl_xor_sync(0xffffffffu, ss, o);
        dd += __shfl_xor_sync(0xffffffffu, dd, o);
        sd += __shfl_xor_sync(0xffffffffu, sd, o);
    }
    float cosv = sd / (fmaxf(sqrtf(ss), EPSN) * fmaxf(sqrtf(dd), EPSN));
    const float4 w0 = *(const float4*)(W2 + (size_t)e * 256 + l * 4);
    const float4 w1 = *(const float4*)(W2 + (size_t)e * 256 + 128 + l * 4);
    float4 m0, m1;
    m0.x = cosv * w0.x * s0.x; m0.y = cosv * w0.y * s0.y;
    m0.z = cosv * w0.z * s0.z; m0.w = cosv * w0.w * s0.w;
    m1.x = cosv * w1.x * s1v.x; m1.y = cosv * w1.y * s1v.y;
    m1.z = cosv * w1.z * s1v.z; m1.w = cosv * w1.w * s1v.w;
    *(float4*)(M2 + (size_t)e * 256 + l * 4) = m0;
    *(float4*)(M2 + (size_t)e * 256 + 128 + l * 4) = m1;
}

__global__ void build1_k(const float* __restrict__ nf, const float* __restrict__ s1,
                         const float* __restrict__ cnt, float* __restrict__ A1) {
    int idx = blockIdx.x * blockDim.x + threadIdx.x;
    if (idx >= NODES * 64) return;
    int n = idx >> 6;
    int c = (idx & 63) * 4;
    float4 v;
    if (c < 128) {
        v = *(const float4*)(nf + (size_t)n * 128 + c);
    } else {
        float inv = 1.0f / fmaxf(cnt[n], 1.0f);
        float4 t = *(const float4*)(s1 + (size_t)n * 128 + (c - 128));
        v = make_float4(t.x * inv, t.y * inv, t.z * inv, t.w * inv);
    }
    *(float4*)(A1 + (size_t)n * 256 + c) = v;
}

__global__ void build2_k(const float* __restrict__ h1, const float* __restrict__ s2,
                         const float* __restrict__ cnt, float* __restrict__ A2) {
    int idx = blockIdx.x * blockDim.x + threadIdx.x;
    if (idx >= NODES * 128) return;
    int n = idx >> 7;
    int c = (idx & 127) * 4;
    float4 v;
    if (c < 256) {
        v = *(const float4*)(h1 + (size_t)n * 256 + c);
    } else {
        float inv = 1.0f / fmaxf(cnt[n], 1.0f);
        float4 t = *(const float4*)(s2 + (size_t)n * 256 + (c - 256));
        v = make_float4(t.x * inv, t.y * inv, t.z * inv, t.w * inv);
    }
    *(float4*)(A2 + (size_t)n * 512 + c) = v;
}

__global__ __launch_bounds__(256) void out_k(const float* __restrict__ A2,
                                             const float* __restrict__ Wl2,
                                             const float* __restrict__ bl2,
                                             float* __restrict__ out) {
    int row = blockIdx.x * 8 + (threadIdx.x >> 5);
    int c = threadIdx.x & 31;
    if (row >= NODES) return;
    const float* a = A2 + (size_t)row * 512;
    float acc = bl2[c];
#pragma unroll 4
    for (int k = 0; k < 512; k += 4) {
        float4 av = *(const float4*)(a + k);
        acc += av.x * Wl2[(k + 0) * 32 + c];
        acc += av.y * Wl2[(k + 1) * 32 + c];
        acc += av.z * Wl2[(k + 2) * 32 + c];
        acc += av.w * Wl2[(k + 3) * 32 + c];
    }
    out[(size_t)row * 32 + c] = acc;
}

// ---------------- launch ----------------
extern "C" void kernel_launch(void* const* d_in, const int* in_sizes, int n_in,
                              void* d_out, int out_size) {
    const float* nf = (const float*)d_in[0];
    const float* ef = (const float*)d_in[1];
    const int* src = (const int*)d_in[2];
    const int* dst = (const int*)d_in[3];
    const float* We1 = (const float*)d_in[4];
    const float* be1 = (const float*)d_in[5];
    const float* Wr1a = (const float*)d_in[6];
    const float* br1a = (const float*)d_in[7];
    const float* Wr1b = (const float*)d_in[8];
    const float* br1b = (const float*)d_in[9];
    const float* Wl1 = (const float*)d_in[10];
    const float* bl1 = (const float*)d_in[11];
    const float* We2 = (const float*)d_in[12];
    const float* be2 = (const float*)d_in[13];
    const float* Wr2a = (const float*)d_in[14];
    const float* br2a = (const float*)d_in[15];
    const float* Wr2b = (const float*)d_in[16];
    const float* br2b = (const float*)d_in[17];
    const float* Wl2 = (const float*)d_in[18];
    const float* bl2 = (const float*)d_in[19];
    float* out = (float*)d_out;

    void *pM1, *pEH, *pR1, *pW2, *pM2, *pR3, *pS1, *pS2, *pH1, *pA1, *pA2, *pCnt;
    void *pT1a, *pT1b, *pTe2, *pT2a, *pT2b, *pTl1;
    cudaGetSymbolAddress(&pM1, g_M1);
    cudaGetSymbolAddress(&pEH, g_EH);
    cudaGetSymbolAddress(&pR1, g_R1);
    cudaGetSymbolAddress(&pW2, g_W2);
    cudaGetSymbolAddress(&pM2, g_M2);
    cudaGetSymbolAddress(&pR3, g_R3);
    cudaGetSymbolAddress(&pS1, g_s1);
    cudaGetSymbolAddress(&pS2, g_s2);
    cudaGetSymbolAddress(&pH1, g_h1);
    cudaGetSymbolAddress(&pA1, g_A1);
    cudaGetSymbolAddress(&pA2, g_A2);
    cudaGetSymbolAddress(&pCnt, g_cnt);
    cudaGetSymbolAddress(&pT1a, g_T1a);
    cudaGetSymbolAddress(&pT1b, g_T1b);
    cudaGetSymbolAddress(&pTe2, g_Te2);
    cudaGetSymbolAddress(&pT2a, g_T2a);
    cudaGetSymbolAddress(&pT2b, g_T2b);
    cudaGetSymbolAddress(&pTl1, g_Tl1);

    // prep
    zero_k<<<(NODES * 256 + 255) / 256, 256>>>((float*)pS1, (float*)pS2, (float*)pCnt);
    cnt_k<<<(EDGES + 255) / 256, 256>>>(dst, (float*)pCnt);
    transp_k<<<(128 * 128 + 255) / 256, 256>>>(Wr1a, (float*)pT1a, 128, 128);
    transp_k<<<(128 * 128 + 255) / 256, 256>>>(Wr1b, (float*)pT1b, 128, 128);
    transp_k<<<(128 * 256 + 255) / 256, 256>>>(We2, (float*)pTe2, 128, 256);
    transp_k<<<(256 * 256 + 255) / 256, 256>>>(Wr2a, (float*)pT2a, 256, 256);
    transp_k<<<(256 * 256 + 255) / 256, 256>>>(Wr2b, (float*)pT2b, 256, 256);
    transp_k<<<(256 * 256 + 255) / 256, 256>>>(Wl1, (float*)pTl1, 256, 256);

    // layer 1
    edge1_k<<<EDGES / 8, 256>>>(nf, ef, src, dst, We1, be1, (float*)pM1, (float*)pEH);
    gemm_mma<1><<<dim3(EDGES / 128, 1), 256>>>((float*)pM1, (float*)pT1a, br1a,
                                               (float*)pR1, EDGES, 128, 128, nullptr);
    gemm_mma<2><<<dim3(EDGES / 128, 1), 256>>>((float*)pR1, (float*)pT1b, br1b,
                                               (float*)pS1, EDGES, 128, 128, dst);
    build1_k<<<(NODES * 64 + 255) / 256, 256>>>(nf, (float*)pS1, (float*)pCnt, (float*)pA1);
    gemm_mma<1><<<dim3((NODES + 127) / 128, 2), 256>>>((float*)pA1, (float*)pTl1, bl1,
                                                       (float*)pH1, NODES, 256, 256, nullptr);
    // layer 2
    gemm_mma<0><<<dim3(EDGES / 128, 2), 256>>>((float*)pEH, (float*)pTe2, be2,
                                               (float*)pW2, EDGES, 128, 256, nullptr);
    edge2_k<<<EDGES / 8, 256>>>(src, dst, (float*)pH1, (float*)pW2, (float*)pM2);
    gemm_mma<1><<<dim3(EDGES / 128, 2), 256>>>((float*)pM2, (float*)pT2a, br2a,
                                               (float*)pR3, EDGES, 256, 256, nullptr);
    gemm_mma<2><<<dim3(EDGES / 128, 2), 256>>>((float*)pR3, (float*)pT2b, br2b,
                                               (float*)pS2, EDGES, 256, 256, dst);
    build2_k<<<(NODES * 128 + 255) / 256, 256>>>((float*)pH1, (float*)pS2, (float*)pCnt,
                                                 (float*)pA2);
    out_k<<<(NODES + 7) / 8, 256>>>((float*)pA2, Wl2, bl2, out);
}

// round 7
// speedup vs baseline: 2.3557x; 1.0956x over previous
#include <cuda_runtime.h>
#include <cstdint>

#define EDGES  800000
#define NODES  50000
#define EPSN   1e-12f

// ---------------- scratch (static device globals; no allocation) ----------------
static __device__ float g_EH[EDGES * 128];   // relu(edge linear 1) -> layer2 edge input
static __device__ float g_W2[EDGES * 256];   // layer2 edge weights
static __device__ float g_cos[EDGES];        // per-edge cosine (layer1 then layer2)
static __device__ float g_s1[NODES * 128];
static __device__ float g_s2[NODES * 256];
static __device__ float g_h1[NODES * 256];
static __device__ float g_A1[NODES * 256];
static __device__ float g_A2[NODES * 512];
static __device__ float g_cnt[NODES];
// transposed weights [N][K] K-major
static __device__ float g_T1a[128 * 128];
static __device__ float g_T1b[128 * 128];
static __device__ float g_Te2[256 * 128];
static __device__ float g_T2a[256 * 256];
static __device__ float g_T2b[256 * 256];
static __device__ float g_Tl1[256 * 256];

// ---------------- mma.sync helpers (sm_80+ features only) ----------------
static __device__ __forceinline__ void mma_tf32(float* c, const uint32_t* a, const uint32_t* b) {
    asm volatile(
        "mma.sync.aligned.m16n8k8.row.col.f32.tf32.tf32.f32 "
        "{%0,%1,%2,%3}, {%4,%5,%6,%7}, {%8,%9}, {%0,%1,%2,%3};"
        : "+f"(c[0]), "+f"(c[1]), "+f"(c[2]), "+f"(c[3])
        : "r"(a[0]), "r"(a[1]), "r"(a[2]), "r"(a[3]), "r"(b[0]), "r"(b[1]));
}
static __device__ __forceinline__ uint32_t f2tf(float f) {
    uint32_t u;
    asm("cvt.rna.tf32.f32 %0, %1;" : "=r"(u) : "f"(f));
    return u;
}
static __device__ __forceinline__ void red2(float* p, float x, float y) {
    asm volatile("red.global.add.v2.f32 [%0], {%1, %2};" :: "l"(p), "f"(x), "f"(y) : "memory");
}

// ---------------- fused per-layer kernel ----------------
// Block owns 128 edge-rows, full width H.
//   tile = message(A-build) -> GEMM1(+b1,relu) -> GEMM2(+b2,relu) -> scatter-add S[dst[row]]
// AMODE 1 (layer1, H=128): a[c] = cos[e] * (e0*We1[0][c]+e1*We1[1][c]+be1[c]) * nf[src[e]][c]
// AMODE 2 (layer2, H=256): a[c] = cos[e] * W2[e][c] * h1[src[e]][c]
template <int H, int AMODE>
__global__ __launch_bounds__(256)
void mlp_fused(const float* __restrict__ X, const float* __restrict__ NF,
               const float* __restrict__ cosv, const int* __restrict__ src,
               const float* __restrict__ Wm, const float* __restrict__ bm,
               const float* __restrict__ W1t, const float* __restrict__ b1,
               const float* __restrict__ W2t, const float* __restrict__ b2,
               float* __restrict__ S, int M, const int* __restrict__ dIdx) {
    constexpr int ST = H + 4;      // Cbuf stride (words): bank = 4r+k -> conflict-free
    constexpr int NT = H / 16;     // n-fragments per warp (warp covers H/2 cols)
    constexpr int NCH = H / 32;    // 32-wide k-chunks
    constexpr int QR = H / 128;    // B row-groups per thread
    extern __shared__ __align__(16) uint32_t smd[];
    uint32_t* Cb = smd;                      // [128][ST] tf32 tile
    uint32_t* Bs = smd + 128 * ST;           // [H][36] weight chunk
    float* sW0 = (float*)(Bs + H * 36);      // AMODE1 edge-linear cache
    float* sW1 = sW0 + 128;
    float* sB  = sW1 + 128;

    const int tid = threadIdx.x;
    const int wid = tid >> 5, lane = tid & 31;
    const int g = lane >> 2, t = lane & 3;
    const int warpM = wid & 3, warpN = wid >> 2;
    const int row0 = blockIdx.x * 128;
    const int lr = tid >> 1, lc = (tid & 1) * 16;

    if (AMODE == 1) {
        if (tid < 128) {
            sW0[tid] = Wm[tid];
            sW1[tid] = Wm[128 + tid];
            sB[tid]  = bm[tid];
        }
        __syncthreads();
    }

    // ---- build message A-tile into Cb (each thread: row lr, 16-col segments) ----
    {
        const int e = row0 + lr;
        const bool av = e < M;
        const float cw = av ? cosv[e] : 0.0f;
        const int sn = av ? src[e] : 0;
        const float* hp = NF + (size_t)sn * H + lc;
        if (AMODE == 1) {
            const float e0 = av ? X[2 * e] : 0.0f;
            const float e1 = av ? X[2 * e + 1] : 0.0f;
#pragma unroll
            for (int j = 0; j < NCH; j++)
#pragma unroll
                for (int i = 0; i < 4; i++) {
                    const int c = lc + j * 32 + i * 4;
                    float4 hv = av ? *(const float4*)(hp + j * 32 + i * 4)
                                   : make_float4(0.f, 0.f, 0.f, 0.f);
                    uint4 u;
                    u.x = f2tf(cw * (e0 * sW0[c+0] + e1 * sW1[c+0] + sB[c+0]) * hv.x);
                    u.y = f2tf(cw * (e0 * sW0[c+1] + e1 * sW1[c+1] + sB[c+1]) * hv.y);
                    u.z = f2tf(cw * (e0 * sW0[c+2] + e1 * sW1[c+2] + sB[c+2]) * hv.z);
                    u.w = f2tf(cw * (e0 * sW0[c+3] + e1 * sW1[c+3] + sB[c+3]) * hv.w);
                    *(uint4*)&Cb[lr * ST + c] = u;
                }
        } else {
            const float* xp = X + (size_t)e * H + lc;
#pragma unroll
            for (int j = 0; j < NCH; j++)
#pragma unroll
                for (int i = 0; i < 4; i++) {
                    const int c = lc + j * 32 + i * 4;
                    float4 xv = av ? *(const float4*)(xp + j * 32 + i * 4)
                                   : make_float4(0.f, 0.f, 0.f, 0.f);
                    float4 hv = av ? *(const float4*)(hp + j * 32 + i * 4)
                                   : make_float4(0.f, 0.f, 0.f, 0.f);
                    uint4 u;
                    u.x = f2tf(cw * xv.x * hv.x);
                    u.y = f2tf(cw * xv.y * hv.y);
                    u.z = f2tf(cw * xv.z * hv.z);
                    u.w = f2tf(cw * xv.w * hv.w);
                    *(uint4*)&Cb[lr * ST + c] = u;
                }
        }
    }

    float acc[2][NT][4];
    float4 stb[QR][4];

#pragma unroll 1
    for (int p = 0; p < 2; p++) {
        const float* W = p ? W2t : W1t;
#pragma unroll
        for (int mt = 0; mt < 2; mt++)
#pragma unroll
            for (int nt = 0; nt < NT; nt++)
#pragma unroll
                for (int i = 0; i < 4; i++) acc[mt][nt][i] = 0.0f;
        // prologue: stage chunk 0 of W
#pragma unroll
        for (int q = 0; q < QR; q++)
#pragma unroll
            for (int i = 0; i < 4; i++)
                stb[q][i] = *(const float4*)(W + (size_t)(q * 128 + lr) * H + lc + i * 4);

        for (int ch = 0; ch < NCH; ch++) {
            __syncthreads();   // Bs free (prev compute done); Cb build/writeback complete
#pragma unroll
            for (int q = 0; q < QR; q++)
#pragma unroll
                for (int i = 0; i < 4; i++) {
                    uint4 u = make_uint4(f2tf(stb[q][i].x), f2tf(stb[q][i].y),
                                         f2tf(stb[q][i].z), f2tf(stb[q][i].w));
                    *(uint4*)&Bs[(q * 128 + lr) * 36 + lc + i * 4] = u;
                }
            __syncthreads();
            if (ch + 1 < NCH) {
#pragma unroll
                for (int q = 0; q < QR; q++)
#pragma unroll
                    for (int i = 0; i < 4; i++)
                        stb[q][i] = *(const float4*)(W + (size_t)(q * 128 + lr) * H +
                                                     (ch + 1) * 32 + lc + i * 4);
            }
#pragma unroll
            for (int kk = 0; kk < 4; kk++) {
                const int ka = ch * 32 + kk * 8;
                uint32_t af[2][4];
#pragma unroll
                for (int mt = 0; mt < 2; mt++) {
                    const int r = warpM * 32 + mt * 16 + g;
                    af[mt][0] = Cb[r * ST + ka + t];
                    af[mt][1] = Cb[(r + 8) * ST + ka + t];
                    af[mt][2] = Cb[r * ST + ka + t + 4];
                    af[mt][3] = Cb[(r + 8) * ST + ka + t + 4];
                }
#pragma unroll
                for (int nt = 0; nt < NT; nt++) {
                    const int n = warpN * (H / 2) + nt * 8 + g;
                    uint32_t bf[2] = { Bs[n * 36 + kk * 8 + t], Bs[n * 36 + kk * 8 + t + 4] };
                    mma_tf32(acc[0][nt], af[0], bf);
                    mma_tf32(acc[1][nt], af[1], bf);
                }
            }
        }
        __syncthreads();   // all compute done before Cb overwrite
        if (p == 0) {
            // relu(acc + b1) -> Cb (tf32) as phase-2 A operand
#pragma unroll
            for (int mt = 0; mt < 2; mt++) {
                const int rl = warpM * 32 + mt * 16 + g;
#pragma unroll
                for (int nt = 0; nt < NT; nt++) {
                    const int cn = warpN * (H / 2) + nt * 8 + t * 2;
                    const float b0 = b1[cn], bb1 = b1[cn + 1];
                    uint2 u0, u1;
                    u0.x = f2tf(fmaxf(acc[mt][nt][0] + b0, 0.f));
                    u0.y = f2tf(fmaxf(acc[mt][nt][1] + bb1, 0.f));
                    u1.x = f2tf(fmaxf(acc[mt][nt][2] + b0, 0.f));
                    u1.y = f2tf(fmaxf(acc[mt][nt][3] + bb1, 0.f));
                    *(uint2*)&Cb[rl * ST + cn] = u0;
                    *(uint2*)&Cb[(rl + 8) * ST + cn] = u1;
                }
            }
        }
    }

    // ---- epilogue: relu(acc + b2) scatter-add to S[dIdx[row]] ----
#pragma unroll
    for (int mt = 0; mt < 2; mt++) {
        const int r0 = row0 + warpM * 32 + mt * 16 + g;
        const bool v0 = r0 < M, v1 = (r0 + 8) < M;
        const int dn0 = v0 ? dIdx[r0] : 0;
        const int dn1 = v1 ? dIdx[r0 + 8] : 0;
#pragma unroll
        for (int nt = 0; nt < NT; nt++) {
            const int cn = warpN * (H / 2) + nt * 8 + t * 2;
            const float b0 = b2[cn], bb1 = b2[cn + 1];
            float va = fmaxf(acc[mt][nt][0] + b0, 0.f);
            float vb = fmaxf(acc[mt][nt][1] + bb1, 0.f);
            float vc = fmaxf(acc[mt][nt][2] + b0, 0.f);
            float vd = fmaxf(acc[mt][nt][3] + bb1, 0.f);
            if (v0) red2(S + (size_t)dn0 * H + cn, va, vb);
            if (v1) red2(S + (size_t)dn1 * H + cn, vc, vd);
        }
    }
}

// ---------------- unfused tensor-core GEMM (node linears, W2 GEMM) ----------------
template <int MODE>   // 0: store; 1: store relu
__global__ __launch_bounds__(256)
void gemm_mma(const float* __restrict__ A, const float* __restrict__ Bt,
              const float* __restrict__ bias, float* __restrict__ C,
              int M, int K, int NT) {
    __shared__ uint32_t As[128][36];
    __shared__ uint32_t Bs[128][36];
    const int tid = threadIdx.x;
    const int wid = tid >> 5, lane = tid & 31;
    const int g = lane >> 2, t = lane & 3;
    const int warpM = wid & 3, warpN = wid >> 2;
    const int row0 = blockIdx.x * 128;
    const int col0 = blockIdx.y * 128;

    float c[2][8][4];
#pragma unroll
    for (int mt = 0; mt < 2; mt++)
#pragma unroll
        for (int nt = 0; nt < 8; nt++)
#pragma unroll
            for (int i = 0; i < 4; i++) c[mt][nt][i] = 0.0f;

    const int lrow = tid >> 1;
    const int lcol = (tid & 1) * 16;
    const bool av = (row0 + lrow) < M;
    const float* apt = A + (size_t)(row0 + lrow) * K + lcol;
    const float* bpt = Bt + (size_t)(col0 + lrow) * K + lcol;

    float4 ra[4], rb[4];
    const int nchunks = K >> 5;
#pragma unroll
    for (int i = 0; i < 4; i++) {
        ra[i] = av ? *(const float4*)(apt + i * 4) : make_float4(0.f, 0.f, 0.f, 0.f);
        rb[i] = *(const float4*)(bpt + i * 4);
    }
    for (int ch = 0; ch < nchunks; ch++) {
        __syncthreads();
#pragma unroll
        for (int i = 0; i < 4; i++) {
            uint4 ua = make_uint4(f2tf(ra[i].x), f2tf(ra[i].y), f2tf(ra[i].z), f2tf(ra[i].w));
            uint4 ub = make_uint4(f2tf(rb[i].x), f2tf(rb[i].y), f2tf(rb[i].z), f2tf(rb[i].w));
            *(uint4*)&As[lrow][lcol + i * 4] = ua;
            *(uint4*)&Bs[lrow][lcol + i * 4] = ub;
        }
        __syncthreads();
        if (ch + 1 < nchunks) {
            const float* an = apt + (ch + 1) * 32;
            const float* bn = bpt + (ch + 1) * 32;
#pragma unroll
            for (int i = 0; i < 4; i++) {
                ra[i] = av ? *(const float4*)(an + i * 4) : make_float4(0.f, 0.f, 0.f, 0.f);
                rb[i] = *(const float4*)(bn + i * 4);
            }
        }
#pragma unroll
        for (int kk = 0; kk < 4; kk++) {
            const int k8 = kk * 8;
            uint32_t af[2][4], bf[8][2];
#pragma unroll
            for (int mt = 0; mt < 2; mt++) {
                const int r = warpM * 32 + mt * 16 + g;
                af[mt][0] = As[r][k8 + t];
                af[mt][1] = As[r + 8][k8 + t];
                af[mt][2] = As[r][k8 + t + 4];
                af[mt][3] = As[r + 8][k8 + t + 4];
            }
#pragma unroll
            for (int nt = 0; nt < 8; nt++) {
                const int n = warpN * 64 + nt * 8 + g;
                bf[nt][0] = Bs[n][k8 + t];
                bf[nt][1] = Bs[n][k8 + t + 4];
            }
#pragma unroll
            for (int mt = 0; mt < 2; mt++)
#pragma unroll
                for (int nt = 0; nt < 8; nt++)
                    mma_tf32(c[mt][nt], af[mt], bf[nt]);
        }
    }
#pragma unroll
    for (int mt = 0; mt < 2; mt++) {
        const int r0 = row0 + warpM * 32 + mt * 16 + g;
        const bool v0r = r0 < M, v1r = (r0 + 8) < M;
#pragma unroll
        for (int nt = 0; nt < 8; nt++) {
            const int cn = col0 + warpN * 64 + nt * 8 + t * 2;
            const float b0 = bias[cn], b1 = bias[cn + 1];
            float v0 = c[mt][nt][0] + b0, v1 = c[mt][nt][1] + b1;
            float v2 = c[mt][nt][2] + b0, v3 = c[mt][nt][3] + b1;
            if (MODE >= 1) {
                v0 = fmaxf(v0, 0.f); v1 = fmaxf(v1, 0.f);
                v2 = fmaxf(v2, 0.f); v3 = fmaxf(v3, 0.f);
            }
            if (v0r) *(float2*)(C + (size_t)r0 * NT + cn) = make_float2(v0, v1);
            if (v1r) *(float2*)(C + (size_t)(r0 + 8) * NT + cn) = make_float2(v2, v3);
        }
    }
}

// ---------------- small kernels ----------------
__global__ void zero_k(float* s1, float* s2, float* cnt) {
    int i = blockIdx.x * blockDim.x + threadIdx.x;
    if (i < NODES * 128) s1[i] = 0.0f;
    if (i < NODES * 256) s2[i] = 0.0f;
    if (i < NODES) cnt[i] = 0.0f;
}

__global__ void cnt_k(const int* __restrict__ dst, float* __restrict__ cnt) {
    int i = blockIdx.x * blockDim.x + threadIdx.x;
    if (i < EDGES) atomicAdd(&cnt[dst[i]], 1.0f);
}

__global__ void transp_k(const float* __restrict__ in, float* __restrict__ out, int K, int N) {
    int i = blockIdx.x * blockDim.x + threadIdx.x;
    if (i < K * N) {
        int k = i / N, n = i % N;
        out[(size_t)n * K + k] = in[i];
    }
}

// layer1: cos + EH (relu edge-linear); no message store
__global__ __launch_bounds__(256) void edge1cos_k(
    const float* __restrict__ nf, const float* __restrict__ ef,
    const int* __restrict__ src, const int* __restrict__ dst,
    const float* __restrict__ We1, const float* __restrict__ be1,
    float* __restrict__ EH, float* __restrict__ cosA) {
    int e = blockIdx.x * 8 + (threadIdx.x >> 5);
    if (e >= EDGES) return;
    int l = threadIdx.x & 31;
    int s = src[e], d = dst[e];
    const float4 hs = *(const float4*)(nf + (size_t)s * 128 + l * 4);
    const float4 hd = *(const float4*)(nf + (size_t)d * 128 + l * 4);
    float ss = hs.x * hs.x + hs.y * hs.y + hs.z * hs.z + hs.w * hs.w;
    float dd = hd.x * hd.x + hd.y * hd.y + hd.z * hd.z + hd.w * hd.w;
    float sd = hs.x * hd.x + hs.y * hd.y + hs.z * hd.z + hs.w * hd.w;
#pragma unroll
    for (int o = 16; o > 0; o >>= 1) {
        ss += __shfl_xor_sync(0xffffffffu, ss, o);
        dd += __shfl_xor_sync(0xffffffffu, dd, o);
        sd += __shfl_xor_sync(0xffffffffu, sd, o);
    }
    float cosv = sd / (fmaxf(sqrtf(ss), EPSN) * fmaxf(sqrtf(dd), EPSN));
    if (l == 0) cosA[e] = cosv;
    float e0 = ef[2 * e], e1 = ef[2 * e + 1];
    int j = l * 4;
    float4 r;
    r.x = fmaxf(e0 * We1[j + 0] + e1 * We1[128 + j + 0] + be1[j + 0], 0.0f);
    r.y = fmaxf(e0 * We1[j + 1] + e1 * We1[128 + j + 1] + be1[j + 1], 0.0f);
    r.z = fmaxf(e0 * We1[j + 2] + e1 * We1[128 + j + 2] + be1[j + 2], 0.0f);
    r.w = fmaxf(e0 * We1[j + 3] + e1 * We1[128 + j + 3] + be1[j + 3], 0.0f);
    *(float4*)(EH + (size_t)e * 128 + j) = r;
}

// layer2: cos only (over h1, 256 wide)
__global__ __launch_bounds__(256) void edge2cos_k(
    const int* __restrict__ src, const int* __restrict__ dst,
    const float* __restrict__ h1, float* __restrict__ cosA) {
    int e = blockIdx.x * 8 + (threadIdx.x >> 5);
    if (e >= EDGES) return;
    int l = threadIdx.x & 31;
    int s = src[e], d = dst[e];
    const float4 s0 = *(const float4*)(h1 + (size_t)s * 256 + l * 4);
    const float4 s1v = *(const float4*)(h1 + (size_t)s * 256 + 128 + l * 4);
    const float4 d0 = *(const float4*)(h1 + (size_t)d * 256 + l * 4);
    const float4 d1 = *(const float4*)(h1 + (size_t)d * 256 + 128 + l * 4);
    float ss = s0.x * s0.x + s0.y * s0.y + s0.z * s0.z + s0.w * s0.w
             + s1v.x * s1v.x + s1v.y * s1v.y + s1v.z * s1v.z + s1v.w * s1v.w;
    float dd = d0.x * d0.x + d0.y * d0.y + d0.z * d0.z + d0.w * d0.w
             + d1.x * d1.x + d1.y * d1.y + d1.z * d1.z + d1.w * d1.w;
    float sd = s0.x * d0.x + s0.y * d0.y + s0.z * d0.z + s0.w * d0.w
             + s1v.x * d1.x + s1v.y * d1.y + s1v.z * d1.z + s1v.w * d1.w;
#pragma unroll
    for (int o = 16; o > 0; o >>= 1) {
        ss += __shfl_xor_sync(0xffffffffu, ss, o);
        dd += __shfl_xor_sync(0xffffffffu, dd, o);
        sd += __shfl_xor_sync(0xffffffffu, sd, o);
    }
    if (l == 0)
        cosA[e] = sd / (fmaxf(sqrtf(ss), EPSN) * fmaxf(sqrtf(dd), EPSN));
}

__global__ void build1_k(const float* __restrict__ nf, const float* __restrict__ s1,
                         const float* __restrict__ cnt, float* __restrict__ A1) {
    int idx = blockIdx.x * blockDim.x + threadIdx.x;
    if (idx >= NODES * 64) return;
    int n = idx >> 6;
    int c = (idx & 63) * 4;
    float4 v;
    if (c < 128) {
        v = *(const float4*)(nf + (size_t)n * 128 + c);
    } else {
        float inv = 1.0f / fmaxf(cnt[n], 1.0f);
        float4 t = *(const float4*)(s1 + (size_t)n * 128 + (c - 128));
        v = make_float4(t.x * inv, t.y * inv, t.z * inv, t.w * inv);
    }
    *(float4*)(A1 + (size_t)n * 256 + c) = v;
}

__global__ void build2_k(const float* __restrict__ h1, const float* __restrict__ s2,
                         const float* __restrict__ cnt, float* __restrict__ A2) {
    int idx = blockIdx.x * blockDim.x + threadIdx.x;
    if (idx >= NODES * 128) return;
    int n = idx >> 7;
    int c = (idx & 127) * 4;
    float4 v;
    if (c < 256) {
        v = *(const float4*)(h1 + (size_t)n * 256 + c);
    } else {
        float inv = 1.0f / fmaxf(cnt[n], 1.0f);
        float4 t = *(const float4*)(s2 + (size_t)n * 256 + (c - 256));
        v = make_float4(t.x * inv, t.y * inv, t.z * inv, t.w * inv);
    }
    *(float4*)(A2 + (size_t)n * 512 + c) = v;
}

__global__ __launch_bounds__(256) void out_k(const float* __restrict__ A2,
                                             const float* __restrict__ Wl2,
                                             const float* __restrict__ bl2,
                                             float* __restrict__ out) {
    int row = blockIdx.x * 8 + (threadIdx.x >> 5);
    int c = threadIdx.x & 31;
    if (row >= NODES) return;
    const float* a = A2 + (size_t)row * 512;
    float acc = bl2[c];
#pragma unroll 4
    for (int k = 0; k < 512; k += 4) {
        float4 av = *(const float4*)(a + k);
        acc += av.x * Wl2[(k + 0) * 32 + c];
        acc += av.y * Wl2[(k + 1) * 32 + c];
        acc += av.z * Wl2[(k + 2) * 32 + c];
        acc += av.w * Wl2[(k + 3) * 32 + c];
    }
    out[(size_t)row * 32 + c] = acc;
}

// ---------------- launch ----------------
extern "C" void kernel_launch(void* const* d_in, const int* in_sizes, int n_in,
                              void* d_out, int out_size) {
    const float* nf = (const float*)d_in[0];
    const float* ef = (const float*)d_in[1];
    const int* src = (const int*)d_in[2];
    const int* dst = (const int*)d_in[3];
    const float* We1 = (const float*)d_in[4];
    const float* be1 = (const float*)d_in[5];
    const float* Wr1a = (const float*)d_in[6];
    const float* br1a = (const float*)d_in[7];
    const float* Wr1b = (const float*)d_in[8];
    const float* br1b = (const float*)d_in[9];
    const float* Wl1 = (const float*)d_in[10];
    const float* bl1 = (const float*)d_in[11];
    const float* We2 = (const float*)d_in[12];
    const float* be2 = (const float*)d_in[13];
    const float* Wr2a = (const float*)d_in[14];
    const float* br2a = (const float*)d_in[15];
    const float* Wr2b = (const float*)d_in[16];
    const float* br2b = (const float*)d_in[17];
    const float* Wl2 = (const float*)d_in[18];
    const float* bl2 = (const float*)d_in[19];
    float* out = (float*)d_out;

    void *pEH, *pW2, *pCos, *pS1, *pS2, *pH1, *pA1, *pA2, *pCnt;
    void *pT1a, *pT1b, *pTe2, *pT2a, *pT2b, *pTl1;
    cudaGetSymbolAddress(&pEH, g_EH);
    cudaGetSymbolAddress(&pW2, g_W2);
    cudaGetSymbolAddress(&pCos, g_cos);
    cudaGetSymbolAddress(&pS1, g_s1);
    cudaGetSymbolAddress(&pS2, g_s2);
    cudaGetSymbolAddress(&pH1, g_h1);
    cudaGetSymbolAddress(&pA1, g_A1);
    cudaGetSymbolAddress(&pA2, g_A2);
    cudaGetSymbolAddress(&pCnt, g_cnt);
    cudaGetSymbolAddress(&pT1a, g_T1a);
    cudaGetSymbolAddress(&pT1b, g_T1b);
    cudaGetSymbolAddress(&pTe2, g_Te2);
    cudaGetSymbolAddress(&pT2a, g_T2a);
    cudaGetSymbolAddress(&pT2b, g_T2b);
    cudaGetSymbolAddress(&pTl1, g_Tl1);

    // dynamic SMEM sizes for fused kernels
    const int SMF1 = (128 * 132 + 128 * 36) * 4 + 3 * 128 * 4;   // 87,552
    const int SMF2 = (128 * 260 + 256 * 36) * 4;                 // 169,984
    cudaFuncSetAttribute(mlp_fused<128, 1>, cudaFuncAttributeMaxDynamicSharedMemorySize, SMF1);
    cudaFuncSetAttribute(mlp_fused<256, 2>, cudaFuncAttributeMaxDynamicSharedMemorySize, SMF2);

    // prep
    zero_k<<<(NODES * 256 + 255) / 256, 256>>>((float*)pS1, (float*)pS2, (float*)pCnt);
    cnt_k<<<(EDGES + 255) / 256, 256>>>(dst, (float*)pCnt);
    transp_k<<<(128 * 128 + 255) / 256, 256>>>(Wr1a, (float*)pT1a, 128, 128);
    transp_k<<<(128 * 128 + 255) / 256, 256>>>(Wr1b, (float*)pT1b, 128, 128);
    transp_k<<<(128 * 256 + 255) / 256, 256>>>(We2, (float*)pTe2, 128, 256);
    transp_k<<<(256 * 256 + 255) / 256, 256>>>(Wr2a, (float*)pT2a, 256, 256);
    transp_k<<<(256 * 256 + 255) / 256, 256>>>(Wr2b, (float*)pT2b, 256, 256);
    transp_k<<<(256 * 256 + 255) / 256, 256>>>(Wl1, (float*)pTl1, 256, 256);

    // layer 1
    edge1cos_k<<<EDGES / 8, 256>>>(nf, ef, src, dst, We1, be1, (float*)pEH, (float*)pCos);
    mlp_fused<128, 1><<<EDGES / 128, 256, SMF1>>>(
        ef, nf, (float*)pCos, src, We1, be1,
        (float*)pT1a, br1a, (float*)pT1b, br1b, (float*)pS1, EDGES, dst);
    build1_k<<<(NODES * 64 + 255) / 256, 256>>>(nf, (float*)pS1, (float*)pCnt, (float*)pA1);
    gemm_mma<1><<<dim3((NODES + 127) / 128, 2), 256>>>((float*)pA1, (float*)pTl1, bl1,
                                                       (float*)pH1, NODES, 256, 256);
    // layer 2
    gemm_mma<0><<<dim3(EDGES / 128, 2), 256>>>((float*)pEH, (float*)pTe2, be2,
                                               (float*)pW2, EDGES, 128, 256);
    edge2cos_k<<<EDGES / 8, 256>>>(src, dst, (float*)pH1, (float*)pCos);
    mlp_fused<256, 2><<<EDGES / 128, 256, SMF2>>>(
        (float*)pW2, (float*)pH1, (float*)pCos, src, nullptr, nullptr,
        (float*)pT2a, br2a, (float*)pT2b, br2b, (float*)pS2, EDGES, dst);
    build2_k<<<(NODES * 128 + 255) / 256, 256>>>((float*)pH1, (float*)pS2, (float*)pCnt,
                                                 (float*)pA2);
    out_k<<<(NODES + 7) / 8, 256>>>((float*)pA2, Wl2, bl2, out);
}

// round 10
// speedup vs baseline: 3.1254x; 1.3268x over previous
#include <cuda_runtime.h>
#include <cuda_fp16.h>
#include <cstdint>

#define EDGES  800000
#define NODES  50000
#define EPSN   1e-12f

// ---------------- scratch ----------------
static __device__ __half g_EH[EDGES * 128];   // relu(edge linear 1), half
static __device__ __half g_W2[EDGES * 256];   // layer2 edge weights, half
static __device__ float g_cos[EDGES];
static __device__ float g_s1[NODES * 128];
static __device__ float g_s2[NODES * 256];
static __device__ float g_h1[NODES * 256];
static __device__ float g_A1[NODES * 256];
static __device__ float g_A2[NODES * 512];
static __device__ float g_cnt[NODES];
// transposed weights [N][K] K-major (fp32)
static __device__ float g_T1a[128 * 128];
static __device__ float g_T1b[128 * 128];
static __device__ float g_Te2[256 * 128];
static __device__ float g_T2a[256 * 256];
static __device__ float g_T2b[256 * 256];
static __device__ float g_Tl1[256 * 256];

// ---------------- helpers ----------------
static __device__ __forceinline__ uint32_t f2h2(float x, float y) {
    __half2 h = __floats2half2_rn(x, y);
    return *(uint32_t*)&h;
}
static __device__ __forceinline__ float2 h22f2(uint32_t u) {
    return __half22float2(*(__half2*)&u);
}
static __device__ __forceinline__ void mma_f16(float* c, const uint32_t* a, const uint32_t* b) {
    asm volatile(
        "mma.sync.aligned.m16n8k16.row.col.f32.f16.f16.f32 "
        "{%0,%1,%2,%3}, {%4,%5,%6,%7}, {%8,%9}, {%0,%1,%2,%3};"
        : "+f"(c[0]), "+f"(c[1]), "+f"(c[2]), "+f"(c[3])
        : "r"(a[0]), "r"(a[1]), "r"(a[2]), "r"(a[3]), "r"(b[0]), "r"(b[1]));
}
static __device__ __forceinline__ void red2(float* p, float x, float y) {
    asm volatile("red.global.add.v2.f32 [%0], {%1, %2};" :: "l"(p), "f"(x), "f"(y) : "memory");
}

// ---------------- fused per-layer MLP ----------------
// AMODE 1 (H=128): a[c] = cos*(e0*We1[0][c]+e1*We1[1][c]+be1[c])*nf[src][c]  (X=ef f32)
// AMODE 2 (H=256): a[c] = cos*W2h[e][c]*h1[src][c]                           (X=W2 half)
template <int H, int AMODE>
__global__ __launch_bounds__(256)
void mlp_fused(const void* __restrict__ Xp, const float* __restrict__ NF,
               const float* __restrict__ cosv, const int* __restrict__ src,
               const float* __restrict__ Wm, const float* __restrict__ bm,
               const float* __restrict__ W1t, const float* __restrict__ b1,
               const float* __restrict__ W2t, const float* __restrict__ b2,
               float* __restrict__ S, int M, const int* __restrict__ dIdx) {
    constexpr int CST = H / 2 + 4;   // Cb stride in uint32 (half2) units
    constexpr int NT = H / 16;
    constexpr int NCH = H / 32;
    constexpr int QR = H / 128;
    extern __shared__ __align__(16) uint32_t smd[];
    uint32_t* Cb = smd;                       // [128][CST] half2 tile
    uint32_t* Bs = smd + 128 * CST;           // [H][20] half2 weight chunk
    float* sW0 = (float*)(Bs + H * 20);
    float* sW1 = sW0 + 128;
    float* sB  = sW1 + 128;

    const int tid = threadIdx.x;
    const int wid = tid >> 5, lane = tid & 31;
    const int g = lane >> 2, t = lane & 3;
    const int warpM = wid & 3, warpN = wid >> 2;
    const int row0 = blockIdx.x * 128;
    const int lr = tid >> 1, lc = (tid & 1) * 16;

    if (AMODE == 1) {
        if (tid < 128) {
            sW0[tid] = Wm[tid];
            sW1[tid] = Wm[128 + tid];
            sB[tid]  = bm[tid];
        }
        __syncthreads();
    }

    // ---- build message A-tile (half2) ----
    {
        const int e = row0 + lr;
        const bool av = e < M;
        const float cw = av ? cosv[e] : 0.0f;
        const int sn = av ? src[e] : 0;
        const float* hp = NF + (size_t)sn * H + lc;
        if (AMODE == 1) {
            const float* ef = (const float*)Xp;
            const float e0 = av ? ef[2 * e] : 0.0f;
            const float e1 = av ? ef[2 * e + 1] : 0.0f;
#pragma unroll
            for (int j = 0; j < NCH; j++) {
                uint32_t pk[8];
#pragma unroll
                for (int i = 0; i < 4; i++) {
                    const int c = lc + j * 32 + i * 4;
                    float4 hv = av ? *(const float4*)(hp + j * 32 + i * 4)
                                   : make_float4(0.f, 0.f, 0.f, 0.f);
                    float m0 = cw * (e0 * sW0[c+0] + e1 * sW1[c+0] + sB[c+0]) * hv.x;
                    float m1 = cw * (e0 * sW0[c+1] + e1 * sW1[c+1] + sB[c+1]) * hv.y;
                    float m2 = cw * (e0 * sW0[c+2] + e1 * sW1[c+2] + sB[c+2]) * hv.z;
                    float m3 = cw * (e0 * sW0[c+3] + e1 * sW1[c+3] + sB[c+3]) * hv.w;
                    pk[2*i] = f2h2(m0, m1); pk[2*i+1] = f2h2(m2, m3);
                }
                const int u0 = lr * CST + (lc + j * 32) / 2;
                *(uint4*)&Cb[u0]     = make_uint4(pk[0], pk[1], pk[2], pk[3]);
                *(uint4*)&Cb[u0 + 4] = make_uint4(pk[4], pk[5], pk[6], pk[7]);
            }
        } else {
            const uint32_t* xp = (const uint32_t*)Xp + (size_t)e * (H / 2) + lc / 2;
#pragma unroll
            for (int j = 0; j < NCH; j++) {
                uint32_t pk[8];
#pragma unroll
                for (int i = 0; i < 4; i++) {
                    uint2 xu = av ? *(const uint2*)(xp + j * 16 + i * 2) : make_uint2(0u, 0u);
                    float2 x0 = h22f2(xu.x), x1 = h22f2(xu.y);
                    float4 hv = av ? *(const float4*)(hp + j * 32 + i * 4)
                                   : make_float4(0.f, 0.f, 0.f, 0.f);
                    pk[2*i]   = f2h2(cw * x0.x * hv.x, cw * x0.y * hv.y);
                    pk[2*i+1] = f2h2(cw * x1.x * hv.z, cw * x1.y * hv.w);
                }
                const int u0 = lr * CST + (lc + j * 32) / 2;
                *(uint4*)&Cb[u0]     = make_uint4(pk[0], pk[1], pk[2], pk[3]);
                *(uint4*)&Cb[u0 + 4] = make_uint4(pk[4], pk[5], pk[6], pk[7]);
            }
        }
    }

    float acc[2][NT][4];
    float4 stb[QR][4];

#pragma unroll 1
    for (int p = 0; p < 2; p++) {
        const float* W = p ? W2t : W1t;
#pragma unroll
        for (int mt = 0; mt < 2; mt++)
#pragma unroll
            for (int nt = 0; nt < NT; nt++)
#pragma unroll
                for (int i = 0; i < 4; i++) acc[mt][nt][i] = 0.0f;
#pragma unroll
        for (int q = 0; q < QR; q++)
#pragma unroll
            for (int i = 0; i < 4; i++)
                stb[q][i] = *(const float4*)(W + (size_t)(q * 128 + lr) * H + lc + i * 4);

        for (int ch = 0; ch < NCH; ch++) {
            __syncthreads();
#pragma unroll
            for (int q = 0; q < QR; q++)
#pragma unroll
                for (int i = 0; i < 4; i++) {
                    uint2 u = make_uint2(f2h2(stb[q][i].x, stb[q][i].y),
                                         f2h2(stb[q][i].z, stb[q][i].w));
                    *(uint2*)&Bs[(q * 128 + lr) * 20 + lc / 2 + i * 2] = u;
                }
            __syncthreads();
            if (ch + 1 < NCH) {
#pragma unroll
                for (int q = 0; q < QR; q++)
#pragma unroll
                    for (int i = 0; i < 4; i++)
                        stb[q][i] = *(const float4*)(W + (size_t)(q * 128 + lr) * H +
                                                     (ch + 1) * 32 + lc + i * 4);
            }
#pragma unroll
            for (int kk = 0; kk < 2; kk++) {   // 2 x K=16 per 32-chunk
                const int ab = ch * 16 + kk * 8;
                uint32_t af[2][4];
#pragma unroll
                for (int mt = 0; mt < 2; mt++) {
                    const int r = warpM * 32 + mt * 16 + g;
                    af[mt][0] = Cb[r * CST + ab + t];
                    af[mt][1] = Cb[(r + 8) * CST + ab + t];
                    af[mt][2] = Cb[r * CST + ab + t + 4];
                    af[mt][3] = Cb[(r + 8) * CST + ab + t + 4];
                }
#pragma unroll
                for (int nt = 0; nt < NT; nt++) {
                    const int n = warpN * (H / 2) + nt * 8 + g;
                    uint32_t bf[2] = { Bs[n * 20 + kk * 8 + t], Bs[n * 20 + kk * 8 + t + 4] };
                    mma_f16(acc[0][nt], af[0], bf);
                    mma_f16(acc[1][nt], af[1], bf);
                }
            }
        }
        __syncthreads();
        if (p == 0) {
#pragma unroll
            for (int mt = 0; mt < 2; mt++) {
                const int rl = warpM * 32 + mt * 16 + g;
#pragma unroll
                for (int nt = 0; nt < NT; nt++) {
                    const int cn = warpN * (H / 2) + nt * 8 + t * 2;
                    const float b0 = b1[cn], bb1 = b1[cn + 1];
                    Cb[rl * CST + (cn >> 1)] =
                        f2h2(fmaxf(acc[mt][nt][0] + b0, 0.f), fmaxf(acc[mt][nt][1] + bb1, 0.f));
                    Cb[(rl + 8) * CST + (cn >> 1)] =
                        f2h2(fmaxf(acc[mt][nt][2] + b0, 0.f), fmaxf(acc[mt][nt][3] + bb1, 0.f));
                }
            }
        }
    }

    // ---- epilogue: relu(acc + b2) scatter-add ----
#pragma unroll
    for (int mt = 0; mt < 2; mt++) {
        const int r0 = row0 + warpM * 32 + mt * 16 + g;
        const bool v0 = r0 < M, v1 = (r0 + 8) < M;
        const int dn0 = v0 ? dIdx[r0] : 0;
        const int dn1 = v1 ? dIdx[r0 + 8] : 0;
#pragma unroll
        for (int nt = 0; nt < NT; nt++) {
            const int cn = warpN * (H / 2) + nt * 8 + t * 2;
            const float b0 = b2[cn], bb1 = b2[cn + 1];
            float va = fmaxf(acc[mt][nt][0] + b0, 0.f);
            float vb = fmaxf(acc[mt][nt][1] + bb1, 0.f);
            float vc = fmaxf(acc[mt][nt][2] + b0, 0.f);
            float vd = fmaxf(acc[mt][nt][3] + bb1, 0.f);
            if (v0) red2(S + (size_t)dn0 * H + cn, va, vb);
            if (v1) red2(S + (size_t)dn1 * H + cn, vc, vd);
        }
    }
}

// ---------------- unfused fp16 GEMM ----------------
// MODE 0: A half (EH), C half store, no relu (W2 path)
// MODE 1: A f32,       C f32 store, relu       (h1 path)
template <int MODE>
__global__ __launch_bounds__(256)
void gemm_hmma(const void* __restrict__ Ap, const float* __restrict__ Bt,
               const float* __restrict__ bias, void* __restrict__ Cp,
               int M, int K, int NT) {
    __shared__ uint32_t As[128][20];
    __shared__ uint32_t Bs[128][20];
    const int tid = threadIdx.x;
    const int wid = tid >> 5, lane = tid & 31;
    const int g = lane >> 2, t = lane & 3;
    const int warpM = wid & 3, warpN = wid >> 2;
    const int row0 = blockIdx.x * 128;
    const int col0 = blockIdx.y * 128;
    const int lrow = tid >> 1, lcol = (tid & 1) * 16;

    float c[2][8][4];
#pragma unroll
    for (int mt = 0; mt < 2; mt++)
#pragma unroll
        for (int nt = 0; nt < 8; nt++)
#pragma unroll
            for (int i = 0; i < 4; i++) c[mt][nt][i] = 0.0f;

    const bool av = (row0 + lrow) < M;
    const int nchunks = K >> 5;

    float4 ra[4];   // f32 A staging
    uint4 rah[2];   // half A staging
    float4 rb[4];
    const float* apt = (MODE == 1) ? (const float*)Ap + (size_t)(row0 + lrow) * K + lcol : nullptr;
    const uint32_t* aph = (MODE == 0)
        ? (const uint32_t*)Ap + (size_t)(row0 + lrow) * (K / 2) + lcol / 2 : nullptr;
    const float* bpt = Bt + (size_t)(col0 + lrow) * K + lcol;

    if (MODE == 1) {
#pragma unroll
        for (int i = 0; i < 4; i++)
            ra[i] = av ? *(const float4*)(apt + i * 4) : make_float4(0.f, 0.f, 0.f, 0.f);
    } else {
#pragma unroll
        for (int i = 0; i < 2; i++)
            rah[i] = av ? *(const uint4*)(aph + i * 4) : make_uint4(0u, 0u, 0u, 0u);
    }
#pragma unroll
    for (int i = 0; i < 4; i++) rb[i] = *(const float4*)(bpt + i * 4);

    for (int ch = 0; ch < nchunks; ch++) {
        __syncthreads();
        if (MODE == 1) {
#pragma unroll
            for (int i = 0; i < 4; i++) {
                uint2 u = make_uint2(f2h2(ra[i].x, ra[i].y), f2h2(ra[i].z, ra[i].w));
                *(uint2*)&As[lrow][lcol / 2 + i * 2] = u;
            }
        } else {
            *(uint4*)&As[lrow][lcol / 2]     = rah[0];
            *(uint4*)&As[lrow][lcol / 2 + 4] = rah[1];
        }
#pragma unroll
        for (int i = 0; i < 4; i++) {
            uint2 u = make_uint2(f2h2(rb[i].x, rb[i].y), f2h2(rb[i].z, rb[i].w));
            *(uint2*)&Bs[lrow][lcol / 2 + i * 2] = u;
        }
        __syncthreads();
        if (ch + 1 < nchunks) {
            if (MODE == 1) {
                const float* an = apt + (ch + 1) * 32;
#pragma unroll
                for (int i = 0; i < 4; i++)
                    ra[i] = av ? *(const float4*)(an + i * 4) : make_float4(0.f, 0.f, 0.f, 0.f);
            } else {
                const uint32_t* an = aph + (ch + 1) * 16;
#pragma unroll
                for (int i = 0; i < 2; i++)
                    rah[i] = av ? *(const uint4*)(an + i * 4) : make_uint4(0u, 0u, 0u, 0u);
            }
            const float* bn = bpt + (ch + 1) * 32;
#pragma unroll
            for (int i = 0; i < 4; i++) rb[i] = *(const float4*)(bn + i * 4);
        }
#pragma unroll
        for (int kk = 0; kk < 2; kk++) {
            const int kb = kk * 8;
            uint32_t af[2][4], bf[8][2];
#pragma unroll
            for (int mt = 0; mt < 2; mt++) {
                const int r = warpM * 32 + mt * 16 + g;
                af[mt][0] = As[r][kb + t];
                af[mt][1] = As[r + 8][kb + t];
                af[mt][2] = As[r][kb + t + 4];
                af[mt][3] = As[r + 8][kb + t + 4];
            }
#pragma unroll
            for (int nt = 0; nt < 8; nt++) {
                const int n = warpN * 64 + nt * 8 + g;
                bf[nt][0] = Bs[n][kb + t];
                bf[nt][1] = Bs[n][kb + t + 4];
            }
#pragma unroll
            for (int mt = 0; mt < 2; mt++)
#pragma unroll
                for (int nt = 0; nt < 8; nt++)
                    mma_f16(c[mt][nt], af[mt], bf[nt]);
        }
    }
#pragma unroll
    for (int mt = 0; mt < 2; mt++) {
        const int r0 = row0 + warpM * 32 + mt * 16 + g;
        const bool v0r = r0 < M, v1r = (r0 + 8) < M;
#pragma unroll
        for (int nt = 0; nt < 8; nt++) {
            const int cn = col0 + warpN * 64 + nt * 8 + t * 2;
            const float b0 = bias[cn], b1 = bias[cn + 1];
            float v0 = c[mt][nt][0] + b0, v1 = c[mt][nt][1] + b1;
            float v2 = c[mt][nt][2] + b0, v3 = c[mt][nt][3] + b1;
            if (MODE == 1) {
                v0 = fmaxf(v0, 0.f); v1 = fmaxf(v1, 0.f);
                v2 = fmaxf(v2, 0.f); v3 = fmaxf(v3, 0.f);
                float* C = (float*)Cp;
                if (v0r) *(float2*)(C + (size_t)r0 * NT + cn) = make_float2(v0, v1);
                if (v1r) *(float2*)(C + (size_t)(r0 + 8) * NT + cn) = make_float2(v2, v3);
            } else {
                uint32_t* C = (uint32_t*)Cp;
                if (v0r) C[(size_t)r0 * (NT / 2) + (cn >> 1)] = f2h2(v0, v1);
                if (v1r) C[(size_t)(r0 + 8) * (NT / 2) + (cn >> 1)] = f2h2(v2, v3);
            }
        }
    }
}

// ---------------- small kernels ----------------
__global__ void zero_k(float* s1, float* s2, float* cnt) {
    int i = blockIdx.x * blockDim.x + threadIdx.x;
    if (i < NODES * 128) s1[i] = 0.0f;
    if (i < NODES * 256) s2[i] = 0.0f;
    if (i < NODES) cnt[i] = 0.0f;
}

__global__ void cnt_k(const int* __restrict__ dst, float* __restrict__ cnt) {
    int i = blockIdx.x * blockDim.x + threadIdx.x;
    if (i < EDGES) atomicAdd(&cnt[dst[i]], 1.0f);
}

__global__ void transp_k(const float* __restrict__ in, float* __restrict__ out, int K, int N) {
    int i = blockIdx.x * blockDim.x + threadIdx.x;
    if (i < K * N) {
        int k = i / N, n = i % N;
        out[(size_t)n * K + k] = in[i];
    }
}

__global__ __launch_bounds__(256) void edge1cos_k(
    const float* __restrict__ nf, const float* __restrict__ ef,
    const int* __restrict__ src, const int* __restrict__ dst,
    const float* __restrict__ We1, const float* __restrict__ be1,
    __half* __restrict__ EH, float* __restrict__ cosA) {
    int e = blockIdx.x * 8 + (threadIdx.x >> 5);
    if (e >= EDGES) return;
    int l = threadIdx.x & 31;
    int s = src[e], d = dst[e];
    const float4 hs = *(const float4*)(nf + (size_t)s * 128 + l * 4);
    const float4 hd = *(const float4*)(nf + (size_t)d * 128 + l * 4);
    float ss = hs.x * hs.x + hs.y * hs.y + hs.z * hs.z + hs.w * hs.w;
    float dd = hd.x * hd.x + hd.y * hd.y + hd.z * hd.z + hd.w * hd.w;
    float sd = hs.x * hd.x + hs.y * hd.y + hs.z * hd.z + hs.w * hd.w;
#pragma unroll
    for (int o = 16; o > 0; o >>= 1) {
        ss += __shfl_xor_sync(0xffffffffu, ss, o);
        dd += __shfl_xor_sync(0xffffffffu, dd, o);
        sd += __shfl_xor_sync(0xffffffffu, sd, o);
    }
    float cosv = sd / (fmaxf(sqrtf(ss), EPSN) * fmaxf(sqrtf(dd), EPSN));
    if (l == 0) cosA[e] = cosv;
    float e0 = ef[2 * e], e1 = ef[2 * e + 1];
    int j = l * 4;
    float r0 = fmaxf(e0 * We1[j + 0] + e1 * We1[128 + j + 0] + be1[j + 0], 0.0f);
    float r1 = fmaxf(e0 * We1[j + 1] + e1 * We1[128 + j + 1] + be1[j + 1], 0.0f);
    float r2 = fmaxf(e0 * We1[j + 2] + e1 * We1[128 + j + 2] + be1[j + 2], 0.0f);
    float r3 = fmaxf(e0 * We1[j + 3] + e1 * We1[128 + j + 3] + be1[j + 3], 0.0f);
    uint2 u = make_uint2(f2h2(r0, r1), f2h2(r2, r3));
    *(uint2*)(EH + (size_t)e * 128 + j) = u;
}

__global__ __launch_bounds__(256) void edge2cos_k(
    const int* __restrict__ src, const int* __restrict__ dst,
    const float* __restrict__ h1, float* __restrict__ cosA) {
    int e = blockIdx.x * 8 + (threadIdx.x >> 5);
    if (e >= EDGES) return;
    int l = threadIdx.x & 31;
    int s = src[e], d = dst[e];
    const float4 s0 = *(const float4*)(h1 + (size_t)s * 256 + l * 4);
    const float4 s1v = *(const float4*)(h1 + (size_t)s * 256 + 128 + l * 4);
    const float4 d0 = *(const float4*)(h1 + (size_t)d * 256 + l * 4);
    const float4 d1 = *(const float4*)(h1 + (size_t)d * 256 + 128 + l * 4);
    float ss = s0.x * s0.x + s0.y * s0.y + s0.z * s0.z + s0.w * s0.w
             + s1v.x * s1v.x + s1v.y * s1v.y + s1v.z * s1v.z + s1v.w * s1v.w;
    float dd = d0.x * d0.x + d0.y * d0.y + d0.z * d0.z + d0.w * d0.w
             + d1.x * d1.x + d1.y * d1.y + d1.z * d1.z + d1.w * d1.w;
    float sd = s0.x * d0.x + s0.y * d0.y + s0.z * d0.z + s0.w * d0.w
             + s1v.x * d1.x + s1v.y * d1.y + s1v.z * d1.z + s1v.w * d1.w;
#pragma unroll
    for (int o = 16; o > 0; o >>= 1) {
        ss += __shfl_xor_sync(0xffffffffu, ss, o);
        dd += __shfl_xor_sync(0xffffffffu, dd, o);
        sd += __shfl_xor_sync(0xffffffffu, sd, o);
    }
    if (l == 0)
        cosA[e] = sd / (fmaxf(sqrtf(ss), EPSN) * fmaxf(sqrtf(dd), EPSN));
}

__global__ void build1_k(const float* __restrict__ nf, const float* __restrict__ s1,
                         const float* __restrict__ cnt, float* __restrict__ A1) {
    int idx = blockIdx.x * blockDim.x + threadIdx.x;
    if (idx >= NODES * 64) return;
    int n = idx >> 6;
    int c = (idx & 63) * 4;
    float4 v;
    if (c < 128) {
        v = *(const float4*)(nf + (size_t)n * 128 + c);
    } else {
        float inv = 1.0f / fmaxf(cnt[n], 1.0f);
        float4 t = *(const float4*)(s1 + (size_t)n * 128 + (c - 128));
        v = make_float4(t.x * inv, t.y * inv, t.z * inv, t.w * inv);
    }
    *(float4*)(A1 + (size_t)n * 256 + c) = v;
}

__global__ void build2_k(const float* __restrict__ h1, const float* __restrict__ s2,
                         const float* __restrict__ cnt, float* __restrict__ A2) {
    int idx = blockIdx.x * blockDim.x + threadIdx.x;
    if (idx >= NODES * 128) return;
    int n = idx >> 7;
    int c = (idx & 127) * 4;
    float4 v;
    if (c < 256) {
        v = *(const float4*)(h1 + (size_t)n * 256 + c);
    } else {
        float inv = 1.0f / fmaxf(cnt[n], 1.0f);
        float4 t = *(const float4*)(s2 + (size_t)n * 256 + (c - 256));
        v = make_float4(t.x * inv, t.y * inv, t.z * inv, t.w * inv);
    }
    *(float4*)(A2 + (size_t)n * 512 + c) = v;
}

__global__ __launch_bounds__(256) void out_k(const float* __restrict__ A2,
                                             const float* __restrict__ Wl2,
                                             const float* __restrict__ bl2,
                                             float* __restrict__ out) {
    int row = blockIdx.x * 8 + (threadIdx.x >> 5);
    int c = threadIdx.x & 31;
    if (row >= NODES) return;
    const float* a = A2 + (size_t)row * 512;
    float acc = bl2[c];
#pragma unroll 4
    for (int k = 0; k < 512; k += 4) {
        float4 av = *(const float4*)(a + k);
        acc += av.x * Wl2[(k + 0) * 32 + c];
        acc += av.y * Wl2[(k + 1) * 32 + c];
        acc += av.z * Wl2[(k + 2) * 32 + c];
        acc += av.w * Wl2[(k + 3) * 32 + c];
    }
    out[(size_t)row * 32 + c] = acc;
}

// ---------------- launch ----------------
extern "C" void kernel_launch(void* const* d_in, const int* in_sizes, int n_in,
                              void* d_out, int out_size) {
    const float* nf = (const float*)d_in[0];
    const float* ef = (const float*)d_in[1];
    const int* src = (const int*)d_in[2];
    const int* dst = (const int*)d_in[3];
    const float* We1 = (const float*)d_in[4];
    const float* be1 = (const float*)d_in[5];
    const float* Wr1a = (const float*)d_in[6];
    const float* br1a = (const float*)d_in[7];
    const float* Wr1b = (const float*)d_in[8];
    const float* br1b = (const float*)d_in[9];
    const float* Wl1 = (const float*)d_in[10];
    const float* bl1 = (const float*)d_in[11];
    const float* We2 = (const float*)d_in[12];
    const float* be2 = (const float*)d_in[13];
    const float* Wr2a = (const float*)d_in[14];
    const float* br2a = (const float*)d_in[15];
    const float* Wr2b = (const float*)d_in[16];
    const float* br2b = (const float*)d_in[17];
    const float* Wl2 = (const float*)d_in[18];
    const float* bl2 = (const float*)d_in[19];
    float* out = (float*)d_out;

    void *pEH, *pW2, *pCos, *pS1, *pS2, *pH1, *pA1, *pA2, *pCnt;
    void *pT1a, *pT1b, *pTe2, *pT2a, *pT2b, *pTl1;
    cudaGetSymbolAddress(&pEH, g_EH);
    cudaGetSymbolAddress(&pW2, g_W2);
    cudaGetSymbolAddress(&pCos, g_cos);
    cudaGetSymbolAddress(&pS1, g_s1);
    cudaGetSymbolAddress(&pS2, g_s2);
    cudaGetSymbolAddress(&pH1, g_h1);
    cudaGetSymbolAddress(&pA1, g_A1);
    cudaGetSymbolAddress(&pA2, g_A2);
    cudaGetSymbolAddress(&pCnt, g_cnt);
    cudaGetSymbolAddress(&pT1a, g_T1a);
    cudaGetSymbolAddress(&pT1b, g_T1b);
    cudaGetSymbolAddress(&pTe2, g_Te2);
    cudaGetSymbolAddress(&pT2a, g_T2a);
    cudaGetSymbolAddress(&pT2b, g_T2b);
    cudaGetSymbolAddress(&pTl1, g_Tl1);

    // dynamic smem: Cb [128][H/2+4] + Bs [H][20] (+ weight cache for AMODE1)
    const int SMF1 = (128 * 68 + 128 * 20) * 4 + 3 * 128 * 4;    // ~46.5 KB
    const int SMF2 = (128 * 132 + 256 * 20) * 4;                 // ~88 KB
    cudaFuncSetAttribute(mlp_fused<128, 1>, cudaFuncAttributeMaxDynamicSharedMemorySize, SMF1);
    cudaFuncSetAttribute(mlp_fused<256, 2>, cudaFuncAttributeMaxDynamicSharedMemorySize, SMF2);

    // prep
    zero_k<<<(NODES * 256 + 255) / 256, 256>>>((float*)pS1, (float*)pS2, (float*)pCnt);
    cnt_k<<<(EDGES + 255) / 256, 256>>>(dst, (float*)pCnt);
    transp_k<<<(128 * 128 + 255) / 256, 256>>>(Wr1a, (float*)pT1a, 128, 128);
    transp_k<<<(128 * 128 + 255) / 256, 256>>>(Wr1b, (float*)pT1b, 128, 128);
    transp_k<<<(128 * 256 + 255) / 256, 256>>>(We2, (float*)pTe2, 128, 256);
    transp_k<<<(256 * 256 + 255) / 256, 256>>>(Wr2a, (float*)pT2a, 256, 256);
    transp_k<<<(256 * 256 + 255) / 256, 256>>>(Wr2b, (float*)pT2b, 256, 256);
    transp_k<<<(256 * 256 + 255) / 256, 256>>>(Wl1, (float*)pTl1, 256, 256);

    // layer 1
    edge1cos_k<<<EDGES / 8, 256>>>(nf, ef, src, dst, We1, be1, (__half*)pEH, (float*)pCos);
    mlp_fused<128, 1><<<EDGES / 128, 256, SMF1>>>(
        ef, nf, (float*)pCos, src, We1, be1,
        (float*)pT1a, br1a, (float*)pT1b, br1b, (float*)pS1, EDGES, dst);
    build1_k<<<(NODES * 64 + 255) / 256, 256>>>(nf, (float*)pS1, (float*)pCnt, (float*)pA1);
    gemm_hmma<1><<<dim3((NODES + 127) / 128, 2), 256>>>((float*)pA1, (float*)pTl1, bl1,
                                                        (float*)pH1, NODES, 256, 256);
    // layer 2
    gemm_hmma<0><<<dim3(EDGES / 128, 2), 256>>>(pEH, (float*)pTe2, be2,
                                                pW2, EDGES, 128, 256);
    edge2cos_k<<<EDGES / 8, 256>>>(src, dst, (float*)pH1, (float*)pCos);
    mlp_fused<256, 2><<<EDGES / 128, 256, SMF2>>>(
        pW2, (float*)pH1, (float*)pCos, src, nullptr, nullptr,
        (float*)pT2a, br2a, (float*)pT2b, br2b, (float*)pS2, EDGES, dst);
    build2_k<<<(NODES * 128 + 255) / 256, 256>>>((float*)pH1, (float*)pS2, (float*)pCnt,
                                                 (float*)pA2);
    out_k<<<(NODES + 7) / 8, 256>>>((float*)pA2, Wl2, bl2, out);
}